// round 8
// baseline (speedup 1.0000x reference)
#include <cuda_runtime.h>
#include <cuda_fp16.h>

// Problem constants (fixed shapes)
#define NU 100000
#define NI 50000
#define NN 150000        // NU + NI
#define D  64
#define DE 16
#define NE 1500000
#define NP 14
#define EPS 1e-5f

#define NN2 (2 * NN)     // row counters for both layers
#define NE2 (2 * NE)     // CSR slots for both layers
#define SCAN_BLK 1024
#define NB2 ((NN2 + SCAN_BLK - 1) / SCAN_BLK)  // 293
#define ROWB ((NN + 7) / 8)                     // 18750 (8 warps/block)
#define HISTB ((NE2 / 4 + 255) / 256)           // 2930

// -------- scratch (device globals; no allocation allowed) --------
__device__ __half g_yh0[NN * D];    // LN features layer 0 (fp16)
__device__ __half g_yh1[NN * D];    // LN features layer 1 (fp16)
__device__ __half g_eh [NN * DE];   // eigs fp16
__device__ float  g_x0 [NN * D];    // layer-0 output (fp32 for final avg)
__device__ int    g_cnt[NN2];       // row degrees (both layers)
__device__ int    g_rs [NN2];       // CSR row starts; becomes row ENDS after scatter
__device__ int2   g_ce [NE2];       // CSR: (col, e1 bits)
__device__ int    g_r  [NE2];       // CSR: row per slot (score-side only)
__device__ float  g_e0 [NE2];       // CSR: exp attention score (written by score)
__device__ int    g_part[512];      // scan partials
__device__ int    g_scan_ctr;

// ---------------------------------------------------------------
// K0: zero counters, reset scan counter, eigs -> fp16.
// ---------------------------------------------------------------
__global__ void prep_kernel(const float* __restrict__ eigs)
{
    int i = blockIdx.x * blockDim.x + threadIdx.x;
    if (i == 0) g_scan_ctr = 0;
    if (i < NN2) g_cnt[i] = 0;
    if (i < NN * DE / 2) {
        float2 v = ((const float2*)eigs)[i];
        ((__half2*)g_eh)[i] = __floats2half2_rn(v.x, v.y);
    }
}

// ---------------------------------------------------------------
// K1: fused LN(layer 0) + histogram(both layers).
// g_cnt pre-zeroed in K0 (no in-kernel zeroing — R3's race).
// ---------------------------------------------------------------
__global__ void ln_hist_kernel(const float* __restrict__ ue,
                               const float* __restrict__ ie,
                               const int*   __restrict__ idx)
{
    if (blockIdx.x < ROWB) {
        int row = blockIdx.x * 8 + (threadIdx.x >> 5);
        if (row >= NN) return;
        int lane = threadIdx.x & 31;

        const float* p = (row < NU) ? (ue + (size_t)row * D)
                                    : (ie + (size_t)(row - NU) * D);
        float2 v = ((const float2*)p)[lane];

        float s = v.x + v.y;
        #pragma unroll
        for (int o = 16; o; o >>= 1) s += __shfl_xor_sync(0xffffffffu, s, o);
        float mu = s * (1.0f / D);

        float dx = v.x - mu, dy = v.y - mu;
        float vs = dx * dx + dy * dy;
        #pragma unroll
        for (int o = 16; o; o >>= 1) vs += __shfl_xor_sync(0xffffffffu, vs, o);
        float inv = rsqrtf(vs * (1.0f / D) + EPS);

        ((__half2*)(g_yh0 + (size_t)row * D))[lane] =
            __floats2half2_rn(dx * inv, dy * inv);
    } else {
        int e4 = (blockIdx.x - ROWB) * blockDim.x + threadIdx.x;
        if (e4 < NE2 / 4) {
            int layer = (e4 >= NE / 4);
            const int* rows = idx + (size_t)layer * 2 * NE;
            int4 r4 = ((const int4*)rows)[e4 - layer * (NE / 4)];
            int base = layer * NN;
            atomicAdd(&g_cnt[base + r4.x], 1);
            atomicAdd(&g_cnt[base + r4.y], 1);
            atomicAdd(&g_cnt[base + r4.z], 1);
            atomicAdd(&g_cnt[base + r4.w], 1);
        }
    }
}

// ---------------------------------------------------------------
// K2/K3: exclusive scan of g_cnt[NN2] -> g_rs.
// ---------------------------------------------------------------
__device__ __forceinline__ int warp_incl_scan(int x, int lane)
{
    #pragma unroll
    for (int o = 1; o < 32; o <<= 1) {
        int t = __shfl_up_sync(0xffffffffu, x, o);
        if (lane >= o) x += t;
    }
    return x;
}

__global__ void scan_kernel()
{
    __shared__ int warpsum[32];
    __shared__ int s_total;
    __shared__ int s_isLast;

    int lane = threadIdx.x & 31;
    int wid  = threadIdx.x >> 5;
    int i = blockIdx.x * SCAN_BLK + threadIdx.x;
    int v = (i < NN2) ? g_cnt[i] : 0;

    int inc = warp_incl_scan(v, lane);
    if (lane == 31) warpsum[wid] = inc;
    __syncthreads();
    if (wid == 0) {
        int s  = warpsum[lane];
        int si = warp_incl_scan(s, lane);
        warpsum[lane] = si - s;
        if (lane == 31) s_total = si;
    }
    __syncthreads();
    int excl = inc - v + warpsum[wid];
    if (i < NN2) g_rs[i] = excl;

    if (threadIdx.x == 0) {
        g_part[blockIdx.x] = s_total;
        __threadfence();
        s_isLast = (atomicAdd(&g_scan_ctr, 1) == (int)gridDim.x - 1);
    }
    __syncthreads();

    if (s_isLast) {
        int pv = (threadIdx.x < NB2) ? g_part[threadIdx.x] : 0;
        int inc2 = warp_incl_scan(pv, lane);
        __syncthreads();
        if (lane == 31) warpsum[wid] = inc2;
        __syncthreads();
        if (wid == 0) {
            int s  = warpsum[lane];
            int si = warp_incl_scan(s, lane);
            warpsum[lane] = si - s;
        }
        __syncthreads();
        int excl2 = inc2 - pv + warpsum[wid];
        if (threadIdx.x < NB2) g_part[threadIdx.x] = excl2;
    }
}

__global__ void scan3_kernel()
{
    int i = blockIdx.x * blockDim.x + threadIdx.x;
    if (i >= NN2) return;
    g_rs[i] += g_part[i >> 10];
}

// ---------------------------------------------------------------
// K4: scatter both layers' edges into CSR order. The cursor IS g_rs
// (atomicAdd returns the slot); afterwards g_rs[row] = row END and
// spmm derives start = end - cnt.
// ---------------------------------------------------------------
__global__ void scatter_kernel(const int*   __restrict__ idx,
                               const int*   __restrict__ pt,
                               const float* __restrict__ pw)
{
    int e = blockIdx.x * blockDim.x + threadIdx.x;
    if (e >= NE2) return;
    int layer = (e >= NE);
    int le = e - layer * NE;
    const int* rows = idx + (size_t)layer * 2 * NE;
    int r = __ldg(rows + le);
    int c = __ldg(rows + NE + le);
    int ptv = __ldg(pt + (size_t)layer * NE + le);
    float w = fminf(__expf(__ldg(pw + layer * NP + ptv)), 5.0f);
    int pos = atomicAdd(&g_rs[layer * NN + r], 1);
    g_ce[pos] = make_int2(c, __float_as_int(w));
    g_r [pos] = r;
}

// ---------------------------------------------------------------
// K5: scores over CSR slots (4 lanes/slot). Consecutive slots share
// r -> duplicate yh[r]/eh[r] loads merge in the warp/L1. Writes e0
// coalesced. No atomics (row sums computed in spmm via linearity).
// ---------------------------------------------------------------
__device__ __forceinline__ float dot8h(uint4 a, uint4 b)
{
    const __half2* ah = (const __half2*)&a;
    const __half2* bh = (const __half2*)&b;
    float d = 0.f;
    #pragma unroll
    for (int j = 0; j < 4; j++) {
        float2 af = __half22float2(ah[j]);
        float2 bf = __half22float2(bh[j]);
        d += af.x * bf.x + af.y * bf.y;
    }
    return d;
}

__global__ void score_kernel(const __half* __restrict__ yh,
                             int slotBase,
                             const float* __restrict__ lam)
{
    int t = blockIdx.x * blockDim.x + threadIdx.x;
    int s = t >> 2;
    if (s >= NE) return;
    int slot = slotBase + s;
    int q = t & 3;

    int r = __ldg(&g_r[slot]);
    int c = __ldg(&g_ce[slot]).x;

    const uint4* ar = (const uint4*)(yh + (size_t)r * D);
    const uint4* bc = (const uint4*)(yh + (size_t)c * D);
    float dp = dot8h(__ldg(ar + q), __ldg(bc + q))
             + dot8h(__ldg(ar + q + 4), __ldg(bc + q + 4));

    // eigs fp16: 16 halves/node; lane q covers dims [4q, 4q+4)
    uint2 eu = __ldg((const uint2*)(g_eh + (size_t)r * DE) + q);
    uint2 ev = __ldg((const uint2*)(g_eh + (size_t)c * DE) + q);
    float2 e0f = __half22float2(*(__half2*)&eu.x);
    float2 e1f = __half22float2(*(__half2*)&eu.y);
    float2 f0f = __half22float2(*(__half2*)&ev.x);
    float2 f1f = __half22float2(*(__half2*)&ev.y);
    float ys = e0f.x * f0f.x + e0f.y * f0f.y + e1f.x * f1f.x + e1f.y * f1f.y;

    float elam = __expf(__ldg(lam));
    float p = dp * 0.125f + elam * ys;
    p += __shfl_xor_sync(0xffffffffu, p, 1);
    p += __shfl_xor_sync(0xffffffffu, p, 2);

    if (q == 0)
        g_e0[slot] = fminf(__expf(p), 5.0f);               // clip(exp,-5,5)
}

// ---------------------------------------------------------------
// K6: SpMM warp/row. Accumulates both unnormalized branches AND the
// row sums in one loop (linearity), normalizes at the end.
//   MODE 0: epilogue LN -> yh1 fp16 + x0 fp32.
//   MODE 1: epilogue out = (emb + x0 + x)/3.
// ---------------------------------------------------------------
template<int MODE>
__global__ void spmm_kernel(const __half* __restrict__ yh,
                            int rowBase,
                            const float* __restrict__ ue,
                            const float* __restrict__ ie,
                            float* __restrict__ out)
{
    int row = blockIdx.x * 8 + (threadIdx.x >> 5);
    if (row >= NN) return;
    int lane = threadIdx.x & 31;

    int n  = g_cnt[rowBase + row];
    int st = g_rs [rowBase + row] - n;      // g_rs holds row END after scatter

    float s0 = 0.f, s1 = 0.f;
    float a0x = 0.f, a0y = 0.f, a1x = 0.f, a1y = 0.f;

    int i = 0;
    for (; i + 2 <= n; i += 2) {
        int2  ceA = __ldg(&g_ce[st + i]);
        int2  ceB = __ldg(&g_ce[st + i + 1]);
        float e0A = __ldg(&g_e0[st + i]);
        float e0B = __ldg(&g_e0[st + i + 1]);
        __half2 hA = ((const __half2*)(yh + (size_t)ceA.x * D))[lane];
        __half2 hB = ((const __half2*)(yh + (size_t)ceB.x * D))[lane];
        float e1A = __int_as_float(ceA.y);
        float e1B = __int_as_float(ceB.y);
        float2 vA = __half22float2(hA);
        float2 vB = __half22float2(hB);
        a0x += e0A * vA.x + e0B * vB.x;
        a0y += e0A * vA.y + e0B * vB.y;
        a1x += e1A * vA.x + e1B * vB.x;
        a1y += e1A * vA.y + e1B * vB.y;
        s0 += e0A + e0B;
        s1 += e1A + e1B;
    }
    if (i < n) {
        int2  ce = __ldg(&g_ce[st + i]);
        float e0 = __ldg(&g_e0[st + i]);
        __half2 h = ((const __half2*)(yh + (size_t)ce.x * D))[lane];
        float e1 = __int_as_float(ce.y);
        float2 v = __half22float2(h);
        a0x += e0 * v.x; a0y += e0 * v.y;
        a1x += e1 * v.x; a1y += e1 * v.y;
        s0 += e0; s1 += e1;
    }

    float i0 = 0.5f / ((s0 == 0.f) ? 1.f : s0);
    float i1 = 0.5f / ((s1 == 0.f) ? 1.f : s1);
    float ax = a0x * i0 + a1x * i1;
    float ay = a0y * i0 + a1y * i1;

    if (MODE == 0) {
        // fused LayerNorm -> yh1 (fp16), plus x0 (fp32)
        float s = ax + ay;
        #pragma unroll
        for (int o = 16; o; o >>= 1) s += __shfl_xor_sync(0xffffffffu, s, o);
        float mu = s * (1.0f / D);
        float dx = ax - mu, dy = ay - mu;
        float vs = dx * dx + dy * dy;
        #pragma unroll
        for (int o = 16; o; o >>= 1) vs += __shfl_xor_sync(0xffffffffu, vs, o);
        float inv = rsqrtf(vs * (1.0f / D) + EPS);

        ((float2*)(g_x0 + (size_t)row * D))[lane] = make_float2(ax, ay);
        ((__half2*)(g_yh1 + (size_t)row * D))[lane] =
            __floats2half2_rn(dx * inv, dy * inv);
    } else {
        const float* emb = (row < NU) ? (ue + (size_t)row * D)
                                      : (ie + (size_t)(row - NU) * D);
        float2 e = ((const float2*)emb)[lane];
        float2 x = ((const float2*)(g_x0 + (size_t)row * D))[lane];
        const float t = 1.0f / 3.0f;
        ((float2*)(out + (size_t)row * D))[lane] =
            make_float2((e.x + x.x + ax) * t, (e.y + x.y + ay) * t);
    }
}

extern "C" void kernel_launch(void* const* d_in, const int* in_sizes, int n_in,
                              void* d_out, int out_size)
{
    const float* ue   = (const float*)d_in[0];  // [NU, D]
    const float* ie   = (const float*)d_in[1];  // [NI, D]
    const float* eigs = (const float*)d_in[2];  // [NN, DE]
    const float* lam  = (const float*)d_in[3];  // [2]
    const float* pw   = (const float*)d_in[4];  // [2, NP]
    const int*   idx  = (const int*)  d_in[5];  // [2, 2, NE]
    const int*   pt   = (const int*)  d_in[6];  // [2, NE]
    float* out = (float*)d_out;

    __half* yh0 = nullptr; __half* yh1 = nullptr;
    cudaGetSymbolAddress((void**)&yh0, g_yh0);
    cudaGetSymbolAddress((void**)&yh1, g_yh1);

    int prepT = NN * DE / 2;                     // 1.2M threads (covers NN2)
    prep_kernel   <<<(prepT + 255) / 256, 256>>>(eigs);
    ln_hist_kernel<<<ROWB + HISTB, 256>>>(ue, ie, idx);
    scan_kernel   <<<NB2, SCAN_BLK>>>();
    scan3_kernel  <<<(NN2 + 255) / 256, 256>>>();
    scatter_kernel<<<(NE2 + 255) / 256, 256>>>(idx, pt, pw);

    int scoreB = (NE * 4 + 255) / 256;
    // layer 0
    score_kernel  <<<scoreB, 256>>>(yh0, 0, lam);
    spmm_kernel<0><<<ROWB, 256>>>(yh0, 0, nullptr, nullptr, nullptr);
    // layer 1
    score_kernel  <<<scoreB, 256>>>(yh1, NE, lam + 1);
    spmm_kernel<1><<<ROWB, 256>>>(yh1, NN, ue, ie, out);
}